// round 5
// baseline (speedup 1.0000x reference)
#include <cuda_runtime.h>
#include <mma.h>
#include <cstdint>
#include <cstddef>

using namespace nvcuda;

// Problem constants
#define kT 512
#define kB 64
#define kH 1024
#define kG 3072
#define kL 4

// Recurrence config: 128 CTAs = 64 slices (HS=16 hidden units) x 2 K-halves.
#define HS 16
#define NR 48
#define NCTA2 128
#define RTH2 512                   /* 16 warps: 8 K-groups x 2 N-halves */
#define KH2 512                    /* K per CTA */
#define KI2 64                     /* k-iters (of 8) per CTA */
#define BUF_LD 68
#define SA2_FLOATS (3 * KI2 * 32 * 4)        /* 24576 fragment-packed W */
#define BUF_FLOATS (4 * NR * BUF_LD)         /* 13056 */
#define REC2_SMEM ((SA2_FLOATS + BUF_FLOATS + 512) * 4)   /* 152576 B */

// gi GEMM config (unchanged)
#define GBM 128
#define GBN 128
#define GTH 512
#define GI_SMEM (GBM * GBN * 4)

// ---------------------------------------------------------------------------
// Scratch
// ---------------------------------------------------------------------------
__device__ float g_seqA[kT * kB * kH];
__device__ float g_seqB[kT * kB * kH];
__device__ float g_gi[(size_t)kT * kB * kG];
__device__ float g_hT[2 * kB * kH];          // packed-transposed h ping-pong
__device__ float g_pair[NCTA2][NR * 32];     // cross-pair partial exchange
__device__ unsigned g_pflag[NCTA2];
__device__ unsigned g_count;
__device__ unsigned g_release;

__global__ void reset_bar_kernel() {
  int t = threadIdx.x;
  if (t < NCTA2) g_pflag[t] = 0u;
  if (t == 0) { g_count = 0u; g_release = 0u; }
}

__device__ __forceinline__ void grid_barrier(unsigned idx) {
  __syncthreads();
  if (threadIdx.x == 0) {
    __threadfence();
    unsigned old = atomicAdd(&g_count, 1u);
    if (old == (unsigned)NCTA2 * (idx + 1u) - 1u) {
      __threadfence();
      *(volatile unsigned*)&g_release = idx + 1u;
    } else {
      while (*(volatile unsigned*)&g_release < idx + 1u) { }
    }
    __threadfence();
  }
  __syncthreads();
}

__device__ __forceinline__ float sigmoidf_(float x) {
  return 1.0f / (1.0f + expf(-x));
}

// packed-transposed h index: pairs (j, j+4) adjacent so B-fragment = LDG.64
__device__ __forceinline__ int hT_index(int j, int b) {
  return (((j >> 3) * 64 + b) << 3) + ((j & 3) << 1) + ((j >> 2) & 1);
}

#define MMA_TF32(d, a, b0, b1)                                              \
  asm volatile(                                                             \
      "mma.sync.aligned.m16n8k8.row.col.f32.tf32.tf32.f32 "                 \
      "{%0,%1,%2,%3}, {%4,%5,%6,%7}, {%8,%9}, {%0,%1,%2,%3};"               \
      : "+f"(d[0]), "+f"(d[1]), "+f"(d[2]), "+f"(d[3])                      \
      : "r"(a.x), "r"(a.y), "r"(a.z), "r"(a.w), "r"(b0), "r"(b1))

__global__ void pack_h0_kernel(const float* __restrict__ h0_l) {
  int idx = blockIdx.x * blockDim.x + threadIdx.x;
  int b = idx >> 10;
  int j = idx & (kH - 1);
  g_hT[hT_index(j, b)] = wmma::__float_to_tf32(h0_l[idx]);
}

// ---------------------------------------------------------------------------
// gi GEMM (unchanged from R2)
// ---------------------------------------------------------------------------
__global__ void __launch_bounds__(GTH, 1) gi_kernel(
    const float* __restrict__ A,
    const float* __restrict__ W,
    const float* __restrict__ bi,
    const float* __restrict__ bh,
    float* __restrict__ C) {
  extern __shared__ float cs[];
  const int tid = threadIdx.x;
  const int wid = tid >> 5;
  const int wm = wid >> 2;
  const int wn = wid & 3;
  const int tm = blockIdx.y * GBM;
  const int tn = blockIdx.x * GBN;

  wmma::fragment<wmma::accumulator, 16, 16, 8, float> acc[2][2];
#pragma unroll
  for (int i = 0; i < 2; i++)
#pragma unroll
    for (int j = 0; j < 2; j++) wmma::fill_fragment(acc[i][j], 0.0f);

  const float* ab = A + (size_t)(tm + wm * 32) * kH;
  const float* wb = W + (size_t)(tn + wn * 32) * kH;

#pragma unroll 2
  for (int k = 0; k < kH; k += 8) {
    wmma::fragment<wmma::matrix_a, 16, 16, 8, wmma::precision::tf32, wmma::row_major> fa[2];
    wmma::fragment<wmma::matrix_b, 16, 16, 8, wmma::precision::tf32, wmma::col_major> fb[2];
#pragma unroll
    for (int i = 0; i < 2; i++) {
      wmma::load_matrix_sync(fa[i], ab + (size_t)i * 16 * kH + k, kH);
#pragma unroll
      for (int e = 0; e < 4; e++) fa[i].x[e] = wmma::__float_to_tf32(fa[i].x[e]);
    }
#pragma unroll
    for (int j = 0; j < 2; j++) {
      wmma::load_matrix_sync(fb[j], wb + (size_t)j * 16 * kH + k, kH);
#pragma unroll
      for (int e = 0; e < 4; e++) fb[j].x[e] = wmma::__float_to_tf32(fb[j].x[e]);
    }
#pragma unroll
    for (int i = 0; i < 2; i++)
#pragma unroll
      for (int j = 0; j < 2; j++) wmma::mma_sync(acc[i][j], fa[i], fb[j], acc[i][j]);
  }

#pragma unroll
  for (int i = 0; i < 2; i++)
#pragma unroll
    for (int j = 0; j < 2; j++)
      wmma::store_matrix_sync(cs + (wm * 32 + i * 16) * GBN + wn * 32 + j * 16,
                              acc[i][j], GBN, wmma::mem_row_major);
  __syncthreads();

  for (int e = tid; e < GBM * GBN; e += GTH) {
    int r = e >> 7;
    int c = e & (GBN - 1);
    int n = tn + c;
    float bias = bi[n] + (n < 2 * kH ? bh[n] : 0.0f);
    C[(size_t)(tm + r) * kG + n] = cs[e] + bias;
  }
}

// ---------------------------------------------------------------------------
// Recurrence: pair-split persistent kernel.
// CTA = (slice, khalf). gh_slice[48,64] = W[48,512]@hT_half[512,64] partial;
// partials exchanged between pair members via global; each member does the
// epilogue for its 32-batch half.
// ---------------------------------------------------------------------------
__global__ void __launch_bounds__(RTH2, 1) rec_kernel(
    const float* __restrict__ gi,
    const float* __restrict__ whh_l,
    const float* __restrict__ h0_l,
    float* __restrict__ seq_out,
    float* __restrict__ hfin,
    const float* __restrict__ bhh_l) {
  extern __shared__ float sm[];
  float* sA = sm;                               // [3][KI2][32][4]
  float* bufs = sm + SA2_FLOATS;                // [4][NR][BUF_LD]
  float* hp_s = bufs + BUF_FLOATS;              // [32 b_loc][16 jj]
  const int tid = threadIdx.x;
  const int lane = tid & 31;
  const int wid = tid >> 5;
  const int slice = blockIdx.x >> 1;
  const int kh = blockIdx.x & 1;
  const int j0 = slice * HS;
  const int peer = blockIdx.x ^ 1;

  // Stage W_hh half-slice in A-fragment order (tf32).
  for (int idx = tid; idx < SA2_FLOATS; idx += RTH2) {
    int e = idx & 3;
    int ln = (idx >> 2) & 31;
    int ki = (idx >> 7) & (KI2 - 1);
    int mt = idx >> 13;                          // gate 0..2
    int rr = (ln >> 2) + ((e & 1) << 3);
    int k = kh * KH2 + ki * 8 + (ln & 3) + ((e >> 1) << 2);
    float w = whh_l[(size_t)(mt * kH + j0 + rr) * kH + k];
    sA[idx] = wmma::__float_to_tf32(w);
  }
  // h_prev slice for own batch half (b_loc = tid>>4, jj = tid&15)
  const int b_loc = tid >> 4;
  const int jj = tid & (HS - 1);
  const int b_glob = kh * 32 + b_loc;
  const int jg = j0 + jj;
  hp_s[tid] = h0_l[(size_t)b_glob * kH + jg];
  const float bn = bhh_l[2 * kH + jg];
  __syncthreads();

  const int kg = wid >> 1;          // K group 0..7
  const int nh = wid & 1;           // N half
  const int g4 = lane >> 2;
  const int l4 = lane & 3;
  const uint4* sAv = (const uint4*)sA;
  float* mybuf = bufs + (kg & 3) * (NR * BUF_LD);

  for (int t = 0; t < kT; t++) {
    // gi prefetch (independent of h -> hides DRAM latency under MMA)
    const float* gb = gi + ((size_t)t * kB + b_glob) * kG + jg;
    float gir = __ldg(gb);
    float giz = __ldg(gb + kH);
    float gin = __ldg(gb + 2 * kH);

    const float2* hT = (const float2*)(g_hT + (size_t)(t & 1) * kB * kH);

    float acc[3][4][4];
#pragma unroll
    for (int mt = 0; mt < 3; mt++)
#pragma unroll
      for (int nt = 0; nt < 4; nt++)
#pragma unroll
        for (int e = 0; e < 4; e++) acc[mt][nt][e] = 0.0f;

#pragma unroll
    for (int i = 0; i < 8; i++) {
      int kil = kg * 8 + i;                      // local k-iter
      int kig = kh * KI2 + kil;                  // global k-iter
      uint4 a0 = sAv[(0 * KI2 + kil) * 32 + lane];
      uint4 a1 = sAv[(1 * KI2 + kil) * 32 + lane];
      uint4 a2 = sAv[(2 * KI2 + kil) * 32 + lane];
      uint32_t bx[4], by[4];
#pragma unroll
      for (int nt = 0; nt < 4; nt++) {
        int n = nh * 32 + nt * 8 + g4;
        float2 p = hT[(kig * 64 + n) * 4 + l4];
        bx[nt] = __float_as_uint(p.x);
        by[nt] = __float_as_uint(p.y);
      }
#pragma unroll
      for (int nt = 0; nt < 4; nt++) {
        MMA_TF32(acc[0][nt], a0, bx[nt], by[nt]);
        MMA_TF32(acc[1][nt], a1, bx[nt], by[nt]);
        MMA_TF32(acc[2][nt], a2, bx[nt], by[nt]);
      }
    }

    // Reduce 8 K-groups into 4 buffers (groups 0-3 write, 4-7 add).
    if (kg < 4) {
#pragma unroll
      for (int mt = 0; mt < 3; mt++)
#pragma unroll
        for (int nt = 0; nt < 4; nt++) {
          int row = mt * 16 + g4;
          int col = nh * 32 + nt * 8 + (l4 << 1);
          *(float2*)(mybuf + row * BUF_LD + col) =
              make_float2(acc[mt][nt][0], acc[mt][nt][1]);
          *(float2*)(mybuf + (row + 8) * BUF_LD + col) =
              make_float2(acc[mt][nt][2], acc[mt][nt][3]);
        }
    }
    __syncthreads();
    if (kg >= 4) {
#pragma unroll
      for (int mt = 0; mt < 3; mt++)
#pragma unroll
        for (int nt = 0; nt < 4; nt++) {
          int row = mt * 16 + g4;
          int col = nh * 32 + nt * 8 + (l4 << 1);
          float2* p0 = (float2*)(mybuf + row * BUF_LD + col);
          float2* p1 = (float2*)(mybuf + (row + 8) * BUF_LD + col);
          float2 v0 = *p0, v1 = *p1;
          v0.x += acc[mt][nt][0]; v0.y += acc[mt][nt][1];
          v1.x += acc[mt][nt][2]; v1.y += acc[mt][nt][3];
          *p0 = v0; *p1 = v1;
        }
    }
    __syncthreads();

    // Export partial for the PEER's batch half, then flag.
#pragma unroll
    for (int e = tid; e < NR * 32; e += RTH2) {
      int row = e >> 5;
      int colp = e & 31;
      int bp = (1 - kh) * 32 + colp;
      float v = bufs[0 * NR * BUF_LD + row * BUF_LD + bp] +
                bufs[1 * NR * BUF_LD + row * BUF_LD + bp] +
                bufs[2 * NR * BUF_LD + row * BUF_LD + bp] +
                bufs[3 * NR * BUF_LD + row * BUF_LD + bp];
      g_pair[blockIdx.x][e] = v;
    }
    __threadfence();
    __syncthreads();
    if (tid == 0) *(volatile unsigned*)&g_pflag[blockIdx.x] = (unsigned)(t + 1);

    // Own-half partial sums (overlaps with peer's export).
    float ghr = 0.f, ghz = 0.f, ghn = 0.f;
#pragma unroll
    for (int q = 0; q < 4; q++) {
      const float* bq = bufs + q * NR * BUF_LD;
      ghr += bq[(0 * 16 + jj) * BUF_LD + b_glob];
      ghz += bq[(1 * 16 + jj) * BUF_LD + b_glob];
      ghn += bq[(2 * 16 + jj) * BUF_LD + b_glob];
    }

    // Wait for peer's partial, add it.
    if (tid == 0) {
      while (*(volatile unsigned*)&g_pflag[peer] < (unsigned)(t + 1)) { }
      __threadfence();
    }
    __syncthreads();
    const float* pp = g_pair[peer];
    ghr += pp[(0 * 16 + jj) * 32 + b_loc];
    ghz += pp[(1 * 16 + jj) * 32 + b_loc];
    ghn += pp[(2 * 16 + jj) * 32 + b_loc];

    // Gates
    float hp = hp_s[tid];
    float r = sigmoidf_(gir + ghr);
    float z = sigmoidf_(giz + ghz);
    float n = tanhf(gin + r * (ghn + bn));
    float h = (1.0f - z) * n + z * hp;
    seq_out[(size_t)t * kB * kH + (size_t)b_glob * kH + jg] = h;
    float* hTn = g_hT + (size_t)((t + 1) & 1) * kB * kH;
    hTn[hT_index(jg, b_glob)] = wmma::__float_to_tf32(h);
    hp_s[tid] = h;
    if (t == kT - 1) hfin[(size_t)b_glob * kH + jg] = h;

    grid_barrier((unsigned)t);
  }
}

// ---------------------------------------------------------------------------
// Launch
// ---------------------------------------------------------------------------
extern "C" void kernel_launch(void* const* d_in, const int* in_sizes, int n_in,
                              void* d_out, int out_size) {
  (void)in_sizes; (void)n_in; (void)out_size;
  const float* x   = (const float*)d_in[0];
  const float* h0  = (const float*)d_in[1];
  const float* wih = (const float*)d_in[2];
  const float* whh = (const float*)d_in[3];
  const float* bih = (const float*)d_in[4];
  const float* bhh = (const float*)d_in[5];
  float* out = (float*)d_out;

  float *seqA = nullptr, *seqB = nullptr, *gi = nullptr;
  cudaGetSymbolAddress((void**)&seqA, g_seqA);
  cudaGetSymbolAddress((void**)&seqB, g_seqB);
  cudaGetSymbolAddress((void**)&gi, g_gi);

  cudaFuncSetAttribute(gi_kernel, cudaFuncAttributeMaxDynamicSharedMemorySize, GI_SMEM);
  cudaFuncSetAttribute(rec_kernel, cudaFuncAttributeMaxDynamicSharedMemorySize, REC2_SMEM);

  dim3 ggrid(kG / GBN, (kT * kB) / GBM);
  for (int l = 0; l < kL; l++) {
    const float* in_seq = (l == 0) ? x : ((l & 1) ? seqA : seqB);
    float* out_seq = (l & 1) ? seqB : seqA;
    gi_kernel<<<ggrid, GTH, GI_SMEM>>>(in_seq,
                                       wih + (size_t)l * kG * kH,
                                       bih + (size_t)l * kG,
                                       bhh + (size_t)l * kG,
                                       gi);
    reset_bar_kernel<<<1, 128>>>();
    pack_h0_kernel<<<(kB * kH) / 256, 256>>>(h0 + (size_t)l * kB * kH);
    rec_kernel<<<NCTA2, RTH2, REC2_SMEM>>>(gi,
                                           whh + (size_t)l * kG * kH,
                                           h0 + (size_t)l * kB * kH,
                                           out_seq,
                                           out + (size_t)l * kB * kH,
                                           bhh + (size_t)l * kG);
  }
}

// round 7
// speedup vs baseline: 2.6240x; 2.6240x over previous
#include <cuda_runtime.h>
#include <mma.h>
#include <cstdint>
#include <cstddef>

using namespace nvcuda;

// Problem constants
#define kT 512
#define kB 64
#define kH 1024
#define kG 3072
#define kL 4

// Recurrence config (R3 structure): 64 CTAs x 8 warps, full K per CTA.
#define HS 16
#define NR 48
#define NCTA 64
#define RTH 256
#define KITERS 128
#define GHS_LD 66
#define SA_FLOATS (3 * KITERS * 32 * 4)
#define REC_SMEM ((SA_FLOATS + 2 * NR * GHS_LD) * 4)   /* 221952 B */

// gi GEMM config: 128x128 CTA tile, 8 warps of 64x32, BK=16, double-buffered
#define GI_LDA 36
#define GI2_TH 256
#define GI2_SMEM (2 * 2 * 128 * GI_LDA * 4)   /* 73728 B */

// ---------------------------------------------------------------------------
// Scratch
// ---------------------------------------------------------------------------
__device__ float g_seqA[kT * kB * kH];
__device__ float g_seqB[kT * kB * kH];
__device__ float g_gi[(size_t)kT * kB * kG];
__device__ float g_hT[2 * kB * kH];
__device__ float g_xr[kT * kB * kH];           // tf32-rounded x
__device__ float g_wr[(size_t)kL * kG * kH];   // tf32-rounded w_ih
__device__ unsigned g_count;
__device__ unsigned g_release;

__global__ void reset_bar_kernel() { g_count = 0u; g_release = 0u; }

__device__ __forceinline__ void grid_barrier(unsigned idx) {
  __syncthreads();
  if (threadIdx.x == 0) {
    __threadfence();
    unsigned old = atomicAdd(&g_count, 1u);
    if (old == (unsigned)NCTA * (idx + 1u) - 1u) {
      __threadfence();
      *(volatile unsigned*)&g_release = idx + 1u;
    } else {
      while (*(volatile unsigned*)&g_release < idx + 1u) { }
    }
    __threadfence();
  }
  __syncthreads();
}

__device__ __forceinline__ float sigmoidf_(float x) {
  return 1.0f / (1.0f + expf(-x));
}

__device__ __forceinline__ int hT_index(int j, int b) {
  return (((j >> 3) * 64 + b) << 3) + ((j & 3) << 1) + ((j >> 2) & 1);
}

#define MMA_TF32(d, a, b0, b1)                                              \
  asm volatile(                                                             \
      "mma.sync.aligned.m16n8k8.row.col.f32.tf32.tf32.f32 "                 \
      "{%0,%1,%2,%3}, {%4,%5,%6,%7}, {%8,%9}, {%0,%1,%2,%3};"               \
      : "+f"(d[0]), "+f"(d[1]), "+f"(d[2]), "+f"(d[3])                      \
      : "r"(a.x), "r"(a.y), "r"(a.z), "r"(a.w), "r"(b0), "r"(b1))

__device__ __forceinline__ void cp16(void* sdst, const void* gsrc) {
  uint32_t s = (uint32_t)__cvta_generic_to_shared(sdst);
  asm volatile("cp.async.cg.shared.global [%0], [%1], 16;" :: "r"(s), "l"(gsrc));
}
#define CP_COMMIT asm volatile("cp.async.commit_group;")
#define CP_WAIT1  asm volatile("cp.async.wait_group 1;")

// ---------------------------------------------------------------------------
// tf32 rounding pass (RNA), vectorized
// ---------------------------------------------------------------------------
__global__ void round_copy_kernel(const float4* __restrict__ src,
                                  float4* __restrict__ dst, int n4) {
  int i = blockIdx.x * blockDim.x + threadIdx.x;
  if (i < n4) {
    float4 v = src[i];
    v.x = wmma::__float_to_tf32(v.x);
    v.y = wmma::__float_to_tf32(v.y);
    v.z = wmma::__float_to_tf32(v.z);
    v.w = wmma::__float_to_tf32(v.w);
    dst[i] = v;
  }
}

__global__ void pack_h0_kernel(const float* __restrict__ h0_l) {
  int idx = blockIdx.x * blockDim.x + threadIdx.x;
  int b = idx >> 10;
  int j = idx & (kH - 1);
  g_hT[hT_index(j, b)] = wmma::__float_to_tf32(h0_l[idx]);
}

// ---------------------------------------------------------------------------
// gi GEMM: C[32768, 3072] = A @ W^T + bias. A, W pre-rounded to tf32.
// cp.async double-buffered BK=16 staging; 8 warps, warp tile 64x32.
// ---------------------------------------------------------------------------
__global__ void __launch_bounds__(GI2_TH, 1) gi_kernel(
    const float* __restrict__ A,
    const float* __restrict__ W,
    const float* __restrict__ bi,
    const float* __restrict__ bh,
    float* __restrict__ C) {
  extern __shared__ float s[];
  float* As = s;                         // [2][128*GI_LDA]
  float* Bs = s + 2 * 128 * GI_LDA;      // [2][128*GI_LDA]
  const int tid = threadIdx.x;
  const int lane = tid & 31;
  const int wid = tid >> 5;
  const int wm = wid >> 2;               // 0..1 (64 rows each)
  const int wn = wid & 3;                // 0..3 (32 cols each)
  const int tm = blockIdx.y * 128;
  const int tn = blockIdx.x * 128;

  // bias registers (cols this lane stores)
  float bs_[4][2];
#pragma unroll
  for (int nt = 0; nt < 4; nt++)
#pragma unroll
    for (int j = 0; j < 2; j++) {
      int n = tn + wn * 32 + nt * 8 + ((lane & 3) << 1) + j;
      bs_[nt][j] = bi[n] + (n < 2 * kH ? bh[n] : 0.0f);
    }

  float acc[4][4][4];
#pragma unroll
  for (int mt = 0; mt < 4; mt++)
#pragma unroll
    for (int nt = 0; nt < 4; nt++)
#pragma unroll
      for (int e = 0; e < 4; e++) acc[mt][nt][e] = 0.0f;

  const int lrow = tid >> 2;
  const int lc4 = tid & 3;

  // prologue: stage 0
#pragma unroll
  for (int i = 0; i < 2; i++) {
    int row = lrow + i * 64;
    cp16(As + row * GI_LDA + lc4 * 4, A + (size_t)(tm + row) * kH + lc4 * 4);
    cp16(Bs + row * GI_LDA + lc4 * 4, W + (size_t)(tn + row) * kH + lc4 * 4);
  }
  CP_COMMIT;

  for (int kt = 0; kt < 64; kt++) {
    int cur = kt & 1;
    if (kt < 63) {
      int nxt = cur ^ 1;
      int k0 = (kt + 1) * 16;
#pragma unroll
      for (int i = 0; i < 2; i++) {
        int row = lrow + i * 64;
        cp16(As + nxt * 128 * GI_LDA + row * GI_LDA + lc4 * 4,
             A + (size_t)(tm + row) * kH + k0 + lc4 * 4);
        cp16(Bs + nxt * 128 * GI_LDA + row * GI_LDA + lc4 * 4,
             W + (size_t)(tn + row) * kH + k0 + lc4 * 4);
      }
      CP_COMMIT;
    } else {
      CP_COMMIT;   // empty group keeps wait_group accounting uniform
    }
    CP_WAIT1;
    __syncthreads();

    const float* Ac = As + cur * 128 * GI_LDA;
    const float* Bc = Bs + cur * 128 * GI_LDA;
#pragma unroll
    for (int ks = 0; ks < 16; ks += 8) {
      uint4 af[4];
#pragma unroll
      for (int mt = 0; mt < 4; mt++) {
        int r0 = wm * 64 + mt * 16 + (lane >> 2);
        int c = ks + (lane & 3);
        af[mt].x = __float_as_uint(Ac[r0 * GI_LDA + c]);
        af[mt].y = __float_as_uint(Ac[(r0 + 8) * GI_LDA + c]);
        af[mt].z = __float_as_uint(Ac[r0 * GI_LDA + c + 4]);
        af[mt].w = __float_as_uint(Ac[(r0 + 8) * GI_LDA + c + 4]);
      }
#pragma unroll
      for (int nt = 0; nt < 4; nt++) {
        int n0 = wn * 32 + nt * 8 + (lane >> 2);
        int k = ks + (lane & 3);
        uint32_t b0 = __float_as_uint(Bc[n0 * GI_LDA + k]);
        uint32_t b1 = __float_as_uint(Bc[n0 * GI_LDA + k + 4]);
#pragma unroll
        for (int mt = 0; mt < 4; mt++) MMA_TF32(acc[mt][nt], af[mt], b0, b1);
      }
    }
    __syncthreads();
  }

  // epilogue: direct float2 stores with bias
#pragma unroll
  for (int mt = 0; mt < 4; mt++)
#pragma unroll
    for (int nt = 0; nt < 4; nt++) {
      int r = tm + wm * 64 + mt * 16 + (lane >> 2);
      int n = tn + wn * 32 + nt * 8 + ((lane & 3) << 1);
      *(float2*)&C[(size_t)r * kG + n] =
          make_float2(acc[mt][nt][0] + bs_[nt][0], acc[mt][nt][1] + bs_[nt][1]);
      *(float2*)&C[(size_t)(r + 8) * kG + n] =
          make_float2(acc[mt][nt][2] + bs_[nt][0], acc[mt][nt][3] + bs_[nt][1]);
    }
}

// ---------------------------------------------------------------------------
// Recurrence (R3 structure + gi prefetch + register-resident h)
// ---------------------------------------------------------------------------
__global__ void __launch_bounds__(RTH, 1) rec_kernel(
    const float* __restrict__ gi,
    const float* __restrict__ whh_l,
    const float* __restrict__ h0_l,
    float* __restrict__ seq_out,
    float* __restrict__ hfin,
    const float* __restrict__ bhh_l) {
  extern __shared__ float sm[];
  float* sA = sm;                                 // [3][KITERS][32][4]
  float* buf0 = sm + SA_FLOATS;
  float* buf1 = buf0 + NR * GHS_LD;
  const int tid = threadIdx.x;
  const int lane = tid & 31;
  const int wid = tid >> 5;
  const int j0 = blockIdx.x * HS;

  // Stage W_hh slice in A-fragment order (tf32).
  for (int idx = tid; idx < SA_FLOATS; idx += RTH) {
    int e = idx & 3;
    int ln = (idx >> 2) & 31;
    int ki = (idx >> 7) & (KITERS - 1);
    int mt = idx >> 14;
    int rr = (ln >> 2) + ((e & 1) << 3);
    int k = ki * 8 + (ln & 3) + ((e >> 1) << 2);
    float w = whh_l[(size_t)(mt * kH + j0 + rr) * kH + k];
    sA[idx] = wmma::__float_to_tf32(w);
  }

  // Per-thread epilogue ownership: jj = tid&15, batches (tid>>4)+{0,16,32,48}
  const int jj = tid & (HS - 1);
  const int jg = j0 + jj;
  const float bn = bhh_l[2 * kH + jg];
  float hp[4];
#pragma unroll
  for (int q = 0; q < 4; q++) {
    int b = (tid >> 4) + q * 16;
    hp[q] = h0_l[(size_t)b * kH + jg];
  }
  __syncthreads();

  const int kg = wid & 3;
  const int nh = wid >> 1 >> 1;      // wid>>2? No: keep R3 mapping below
  const int nhh = wid >> 2;          // N half (R3: nh = wid>>2 with kg=wid&3)
  const int g4 = lane >> 2;
  const int l4 = lane & 3;
  const uint4* sAv = (const uint4*)sA;
  (void)nh;

  for (int t = 0; t < kT; t++) {
    // gi prefetch: 12 independent DRAM loads, consumed only in the epilogue
    float gir[4], giz[4], gin[4];
#pragma unroll
    for (int q = 0; q < 4; q++) {
      int b = (tid >> 4) + q * 16;
      const float* gb = gi + ((size_t)t * kB + b) * kG + jg;
      gir[q] = __ldg(gb);
      giz[q] = __ldg(gb + kH);
      gin[q] = __ldg(gb + 2 * kH);
    }

    const float2* hT = (const float2*)(g_hT + (size_t)(t & 1) * kB * kH);

    float acc[3][4][4];
#pragma unroll
    for (int mt = 0; mt < 3; mt++)
#pragma unroll
      for (int nt = 0; nt < 4; nt++)
#pragma unroll
        for (int e = 0; e < 4; e++) acc[mt][nt][e] = 0.0f;

#pragma unroll 2
    for (int i = 0; i < 32; i++) {
      int ki = kg * 32 + i;
      uint4 a0 = sAv[(0 * KITERS + ki) * 32 + lane];
      uint4 a1 = sAv[(1 * KITERS + ki) * 32 + lane];
      uint4 a2 = sAv[(2 * KITERS + ki) * 32 + lane];
      uint32_t bx[4], by[4];
#pragma unroll
      for (int nt = 0; nt < 4; nt++) {
        int n = (nhh * 4 + nt) * 8 + g4;
        float2 p = hT[(ki * 64 + n) * 4 + l4];
        bx[nt] = __float_as_uint(p.x);
        by[nt] = __float_as_uint(p.y);
      }
#pragma unroll
      for (int nt = 0; nt < 4; nt++) {
        MMA_TF32(acc[0][nt], a0, bx[nt], by[nt]);
        MMA_TF32(acc[1][nt], a1, bx[nt], by[nt]);
        MMA_TF32(acc[2][nt], a2, bx[nt], by[nt]);
      }
    }

    float* buf = (kg & 1) ? buf1 : buf0;
    if (kg < 2) {
#pragma unroll
      for (int mt = 0; mt < 3; mt++)
#pragma unroll
        for (int nt = 0; nt < 4; nt++) {
          int row = mt * 16 + g4;
          int col = (nhh * 4 + nt) * 8 + (l4 << 1);
          *(float2*)(buf + row * GHS_LD + col) =
              make_float2(acc[mt][nt][0], acc[mt][nt][1]);
          *(float2*)(buf + (row + 8) * GHS_LD + col) =
              make_float2(acc[mt][nt][2], acc[mt][nt][3]);
        }
    }
    __syncthreads();
    if (kg >= 2) {
#pragma unroll
      for (int mt = 0; mt < 3; mt++)
#pragma unroll
        for (int nt = 0; nt < 4; nt++) {
          int row = mt * 16 + g4;
          int col = (nhh * 4 + nt) * 8 + (l4 << 1);
          float2* p0 = (float2*)(buf + row * GHS_LD + col);
          float2* p1 = (float2*)(buf + (row + 8) * GHS_LD + col);
          float2 v0 = *p0, v1 = *p1;
          v0.x += acc[mt][nt][0]; v0.y += acc[mt][nt][1];
          v1.x += acc[mt][nt][2]; v1.y += acc[mt][nt][3];
          *p0 = v0; *p1 = v1;
        }
    }
    __syncthreads();

    // Gate epilogue: gi already in registers, h register-resident.
    float* hTn = g_hT + (size_t)((t + 1) & 1) * kB * kH;
#pragma unroll
    for (int q = 0; q < 4; q++) {
      int b = (tid >> 4) + q * 16;
      float ghr = buf0[(0 * 16 + jj) * GHS_LD + b] + buf1[(0 * 16 + jj) * GHS_LD + b];
      float ghz = buf0[(1 * 16 + jj) * GHS_LD + b] + buf1[(1 * 16 + jj) * GHS_LD + b];
      float ghn = buf0[(2 * 16 + jj) * GHS_LD + b] + buf1[(2 * 16 + jj) * GHS_LD + b];
      float r = sigmoidf_(gir[q] + ghr);
      float z = sigmoidf_(giz[q] + ghz);
      float n = tanhf(gin[q] + r * (ghn + bn));
      float h = (1.0f - z) * n + z * hp[q];
      hp[q] = h;
      float hr = wmma::__float_to_tf32(h);
      seq_out[(size_t)t * kB * kH + (size_t)b * kH + jg] = hr;  // next-layer gi input
      hTn[hT_index(jg, b)] = hr;
      if (t == kT - 1) hfin[(size_t)b * kH + jg] = h;
    }
    grid_barrier((unsigned)t);
  }
}

// ---------------------------------------------------------------------------
// Launch
// ---------------------------------------------------------------------------
extern "C" void kernel_launch(void* const* d_in, const int* in_sizes, int n_in,
                              void* d_out, int out_size) {
  (void)in_sizes; (void)n_in; (void)out_size;
  const float* x   = (const float*)d_in[0];
  const float* h0  = (const float*)d_in[1];
  const float* wih = (const float*)d_in[2];
  const float* whh = (const float*)d_in[3];
  const float* bih = (const float*)d_in[4];
  const float* bhh = (const float*)d_in[5];
  float* out = (float*)d_out;

  float *seqA = nullptr, *seqB = nullptr, *gi = nullptr, *xr = nullptr, *wr = nullptr;
  cudaGetSymbolAddress((void**)&seqA, g_seqA);
  cudaGetSymbolAddress((void**)&seqB, g_seqB);
  cudaGetSymbolAddress((void**)&gi, g_gi);
  cudaGetSymbolAddress((void**)&xr, g_xr);
  cudaGetSymbolAddress((void**)&wr, g_wr);

  cudaFuncSetAttribute(gi_kernel, cudaFuncAttributeMaxDynamicSharedMemorySize, GI2_SMEM);
  cudaFuncSetAttribute(rec_kernel, cudaFuncAttributeMaxDynamicSharedMemorySize, REC_SMEM);

  // One-time tf32 rounding passes (idempotent, ~65us total)
  {
    int n4x = (kT * kB * kH) / 4;
    round_copy_kernel<<<(n4x + 255) / 256, 256>>>((const float4*)x, (float4*)xr, n4x);
    int n4w = (int)(((size_t)kL * kG * kH) / 4);
    round_copy_kernel<<<(n4w + 255) / 256, 256>>>((const float4*)wih, (float4*)wr, n4w);
  }

  dim3 ggrid(kG / 128, (kT * kB) / 128);
  for (int l = 0; l < kL; l++) {
    const float* in_seq = (l == 0) ? xr : ((l & 1) ? seqA : seqB);
    float* out_seq = (l & 1) ? seqB : seqA;
    gi_kernel<<<ggrid, GI2_TH, GI2_SMEM>>>(in_seq,
                                           wr + (size_t)l * kG * kH,
                                           bih + (size_t)l * kG,
                                           bhh + (size_t)l * kG,
                                           gi);
    reset_bar_kernel<<<1, 1>>>();
    pack_h0_kernel<<<(kB * kH) / 256, 256>>>(h0 + (size_t)l * kB * kH);
    rec_kernel<<<NCTA, RTH, REC_SMEM>>>(gi,
                                        whh + (size_t)l * kG * kH,
                                        h0 + (size_t)l * kB * kH,
                                        out_seq,
                                        out + (size_t)l * kB * kH,
                                        bhh + (size_t)l * kG);
  }
}